// round 6
// baseline (speedup 1.0000x reference)
#include <cuda_runtime.h>

// x: (B=256, F=2048, J=25, C=2) fp32 row-major. Row = 50 floats = 200 B.
// theta = w[0] only (reference's loop returns early). Joints 0..7 rotated:
//   nx = c*x + s*y ; ny = c*y - s*x   (out = x @ [[c,-s],[s,c]])
// Joints 8..24 passthrough. Pairs sit at even float offsets, so every float4
// holds exactly 2 complete (x,y) pairs.
//
// 4 float4s per thread, +256 stride (coalesced), for MLP=4.
// Stores use .cs (evict-first) so the write-only output doesn't evict the
// input's L2 footprint (which is giving real DRAM-traffic savings).

__device__ __forceinline__ void rot2(float& px, float& py, float c, float s) {
    float nx = fmaf(c, px, s * py);
    float ny = fmaf(c, py, -s * px);
    px = nx; py = ny;
}

__device__ __forceinline__ unsigned wrap25(unsigned j) {
    return (j >= 25u) ? j - 25u : j;
}

__global__ void __launch_bounds__(256)
rt_rotate(const float4* __restrict__ x, float4* __restrict__ out,
          const float* __restrict__ w, int n4) {
    const int base = blockIdx.x * 1024 + threadIdx.x;

    float s, c;
    __sincosf(__ldg(w), &s, &c);

    int  i[4];
    bool b[4];
    float4 v[4];
#pragma unroll
    for (int k = 0; k < 4; k++) {
        i[k] = base + k * 256;
        b[k] = i[k] < n4;
        if (b[k]) v[k] = x[i[k]];          // 4 front-batched LDG.128
    }

    // Joint of first pair in v[0]: (2*base) % 25. Each +256 float4s = +512
    // pairs; 512 % 25 == 12.
    unsigned j0 = ((unsigned)base * 2u) % 25u;
#pragma unroll
    for (int k = 0; k < 4; k++) {
        unsigned ja = j0;
        unsigned jb = wrap25(ja + 1u);
        if (ja < 8u) rot2(v[k].x, v[k].y, c, s);
        if (jb < 8u) rot2(v[k].z, v[k].w, c, s);
        j0 = wrap25(j0 + 12u);
    }

#pragma unroll
    for (int k = 0; k < 4; k++)
        if (b[k]) __stcs(&out[i[k]], v[k]);  // STG.128 evict-first
}

extern "C" void kernel_launch(void* const* d_in, const int* in_sizes, int n_in,
                              void* d_out, int out_size) {
    const float* x = (const float*)d_in[0];
    const float* w = (const float*)d_in[1];
    float* out = (float*)d_out;

    int n = in_sizes[0];            // 26,214,400 floats
    int n4 = n / 4;                 // 6,553,600 float4s
    int blocks = (n4 + 1023) / 1024;  // 4 float4s/thread, 256 threads/block
    rt_rotate<<<blocks, 256>>>((const float4*)x, (float4*)out, w, n4);
}

// round 8
// speedup vs baseline: 1.0354x; 1.0354x over previous
#include <cuda_runtime.h>

// x: (B=256, F=2048, J=25, C=2) fp32 row-major. Row = 50 floats = 200 B.
// theta = w[0] only (reference's loop returns early). Joints 0..7 rotated:
//   nx = c*x + s*y ; ny = c*y - s*x   (out = x @ [[c,-s],[s,c]])
// Joints 8..24 passthrough.
//
// sm_100+ 256-bit global ld/st (ld/st.global.v8.f32): each instruction moves
// 8 floats = 4 complete (x,y) pairs. 2 chunks per thread, +blockDim stride.
// Chunk c covers pairs 4c..4c+3; joint = pair % 25.
// Chunk c+256 => pair offset +1024; 1024 % 25 == 24.   (R6 bug: used 23)

struct f8 { float v[8]; };

__device__ __forceinline__ f8 ldg256(const float* p) {
    f8 r;
    asm volatile("ld.global.nc.v8.f32 {%0,%1,%2,%3,%4,%5,%6,%7}, [%8];"
                 : "=f"(r.v[0]), "=f"(r.v[1]), "=f"(r.v[2]), "=f"(r.v[3]),
                   "=f"(r.v[4]), "=f"(r.v[5]), "=f"(r.v[6]), "=f"(r.v[7])
                 : "l"(p));
    return r;
}

__device__ __forceinline__ void stg256(float* p, const f8& r) {
    asm volatile("st.global.v8.f32 [%0], {%1,%2,%3,%4,%5,%6,%7,%8};"
                 :: "l"(p),
                    "f"(r.v[0]), "f"(r.v[1]), "f"(r.v[2]), "f"(r.v[3]),
                    "f"(r.v[4]), "f"(r.v[5]), "f"(r.v[6]), "f"(r.v[7])
                 : "memory");
}

__device__ __forceinline__ void rot2(float& px, float& py, float c, float s) {
    float nx = fmaf(c, px, s * py);
    float ny = fmaf(c, py, -s * px);
    px = nx; py = ny;
}

__device__ __forceinline__ unsigned wrap25(unsigned j) {
    return (j >= 25u) ? j - 25u : j;
}

// Rotate the joint<8 pairs inside one 8-float chunk whose first pair has
// joint index j0 (consecutive pairs, joint wraps at 25).
__device__ __forceinline__ void rot_chunk(f8& a, unsigned j0, float c, float s) {
    unsigned j = j0;
#pragma unroll
    for (int t = 0; t < 4; t++) {
        if (j < 8u) rot2(a.v[2 * t], a.v[2 * t + 1], c, s);
        j = wrap25(j + 1u);
    }
}

__global__ void __launch_bounds__(256)
rt_rotate(const float* __restrict__ x, float* __restrict__ out,
          const float* __restrict__ w, int n8) {
    const int c0 = blockIdx.x * 512 + threadIdx.x;   // first v8 chunk
    const int c1 = c0 + 256;                         // second v8 chunk

    float s, c;
    __sincosf(__ldg(w), &s, &c);

    const bool b0 = c0 < n8;
    const bool b1 = c1 < n8;

    f8 a0, a1;
    if (b0) a0 = ldg256(x + (size_t)c0 * 8);
    if (b1) a1 = ldg256(x + (size_t)c1 * 8);

    unsigned j0 = ((unsigned)c0 * 4u) % 25u;        // joint of chunk0 pair0
    unsigned j1 = wrap25(j0 + 24u);                 // +1024 pairs ≡ +24 mod 25

    if (b0) rot_chunk(a0, j0, c, s);
    if (b1) rot_chunk(a1, j1, c, s);

    if (b0) stg256(out + (size_t)c0 * 8, a0);
    if (b1) stg256(out + (size_t)c1 * 8, a1);
}

extern "C" void kernel_launch(void* const* d_in, const int* in_sizes, int n_in,
                              void* d_out, int out_size) {
    const float* x = (const float*)d_in[0];
    const float* w = (const float*)d_in[1];
    float* out = (float*)d_out;

    int n = in_sizes[0];            // 26,214,400 floats
    int n8 = n / 8;                 // 3,276,800 8-float chunks
    int blocks = (n8 + 511) / 512;  // 2 chunks/thread, 256 threads/block
    rt_rotate<<<blocks, 256>>>(x, out, w, n8);
}